// round 15
// baseline (speedup 1.0000x reference)
#include <cuda_runtime.h>
#include <cuda_fp16.h>
#include <cstdint>

#define DI __device__ __forceinline__

namespace {

constexpr int kT = 28;
constexpr int kI = 28;
constexpr int kH = 128;
constexpr int kC = 10;
constexpr int WARPS = 4;
constexpr int THREADS = WARPS * 32;     // 128
constexpr int GRID = 512;               // 1024 tiles, 2 tiles (warp-pairs)/CTA
constexpr int XROW = kT * kI;           // 784

// SMEM: paired-B fragment tables + per-warp exchange slots
constexpr unsigned OFF_W = 0;                   // [8kt][8ntp][32 lane][16B] = 32768
constexpr unsigned OFF_U = 32768;               // [2kt][8ntp][32][16B]     = 8192
constexpr unsigned OFF_V = 32768 + 8192;        // [8kt][1ntp][32][16B]     = 4096
constexpr unsigned OFF_X = OFF_V + 4096;        // 4 warps * 4096 exchange
constexpr unsigned SMEM_TOTAL = OFF_X + 4 * 4096;  // 61440 -> 3 CTAs/SM

// pack two fp32 -> fp16x2 (lo = a, hi = b)
DI unsigned packh(float a, float b) {
  unsigned d;
  asm("cvt.rn.f16x2.f32 %0, %1, %2;" : "=r"(d) : "f"(b), "f"(a));
  return d;
}
DI unsigned packh2(float2 v) { return packh(v.x, v.y); }

DI unsigned th2(unsigned h2) {  // tanh on fp16x2, one MUFU per 2 elems
  unsigned r;
  asm("tanh.approx.f16x2 %0, %1;" : "=r"(r) : "r"(h2));
  return r;
}

// f16-accumulator MMA: D(f16x2 x2) += A(m16k16 f16) * B(k16n8 f16)
DI void mmah(unsigned* d, const unsigned* a, unsigned bx, unsigned by) {
  asm("mma.sync.aligned.m16n8k16.row.col.f16.f16.f16.f16 "
      "{%0,%1},{%2,%3,%4,%5},{%6,%7},{%0,%1};"
      : "+r"(d[0]), "+r"(d[1])
      : "r"(a[0]), "r"(a[1]), "r"(a[2]), "r"(a[3]), "r"(bx), "r"(by));
}
DI void mmahz(unsigned* d, const unsigned* a, unsigned bx, unsigned by) {
  asm("mma.sync.aligned.m16n8k16.row.col.f16.f16.f16.f16 "
      "{%0,%1},{%2,%3,%4,%5},{%6,%7},{%8,%8};"
      : "=r"(d[0]), "=r"(d[1])
      : "r"(a[0]), "r"(a[1]), "r"(a[2]), "r"(a[3]), "r"(bx), "r"(by),
        "r"(0u));
}
// f32-accumulator MMA (output projection only, outside the hot loop)
DI void mma16(float* c, const unsigned* a, unsigned bx, unsigned by) {
  asm("mma.sync.aligned.m16n8k16.row.col.f32.f16.f16.f32 "
      "{%0,%1,%2,%3},{%4,%5,%6,%7},{%8,%9},{%0,%1,%2,%3};"
      : "+f"(c[0]), "+f"(c[1]), "+f"(c[2]), "+f"(c[3])
      : "r"(a[0]), "r"(a[1]), "r"(a[2]), "r"(a[3]), "r"(bx), "r"(by));
}
DI void mma16z(float* c, const unsigned* a, unsigned bx, unsigned by) {
  asm("mma.sync.aligned.m16n8k16.row.col.f32.f16.f16.f32 "
      "{%0,%1,%2,%3},{%4,%5,%6,%7},{%8,%9},{%10,%10,%10,%10};"
      : "=f"(c[0]), "=f"(c[1]), "=f"(c[2]), "=f"(c[3])
      : "r"(a[0]), "r"(a[1]), "r"(a[2]), "r"(a[3]), "r"(bx), "r"(by),
        "f"(0.0f));
}

// B element (n,k) -> byte offset inside a paired table with `ntpn` nt-pairs
// (kt stride = ntpn * 32 uint4). W: ntpn=8, U: ntpn=8, V: ntpn=1.
DI unsigned bpos(int n, int k, int ntpn) {
  int kt = k >> 4, kk = k & 15, nt = n >> 3, rr = n & 7;
  int ntp = nt >> 1, sel = nt & 1;
  int ln = rr * 4 + ((kk >> 1) & 3);
  return (unsigned)((((kt * ntpn + ntp) * 32 + ln) << 4) + sel * 8 +
                    ((kk >> 3) & 1) * 4 + (kk & 1) * 2);
}

__global__ void __launch_bounds__(THREADS, 3) rnn_kernel(
    const float* __restrict__ x, const float* __restrict__ Uw,
    const float* __restrict__ Ub, const float* __restrict__ Ww,
    const float* __restrict__ Wb, const float* __restrict__ Vw,
    const float* __restrict__ Vb, float* __restrict__ out) {
  extern __shared__ __align__(16) char sm[];
  const int tid = threadIdx.x;
  const int w = tid >> 5, lane = tid & 31;
  const int r = lane >> 2, q = lane & 3;

  // ---- build fp16 paired-B fragment tables, biases folded into U col 28 ----
  for (int idx = tid; idx < kH * kH; idx += THREADS) {  // W^T[k][n] = Ww[n*128+k]
    int n = idx >> 7, k = idx & 127;
    *(__half*)(sm + OFF_W + bpos(n, k, 8)) = __float2half_rn(Ww[idx]);
  }
  for (int idx = tid; idx < kH * 32; idx += THREADS) {  // U^T padded K=32
    int n = idx >> 5, k = idx & 31;
    float v = (k < kI) ? Uw[n * kI + k] : ((k == kI) ? (Ub[n] + Wb[n]) : 0.0f);
    *(__half*)(sm + OFF_U + bpos(n, k, 8)) = __float2half_rn(v);
  }
  for (int idx = tid; idx < 16 * kH; idx += THREADS) {  // V^T padded N=16
    int n = idx >> 7, k = idx & 127;
    float v = (n < kC) ? Vw[n * kH + k] : 0.0f;
    *(__half*)(sm + OFF_V + bpos(n, k, 1)) = __float2half_rn(v);
  }
  __syncthreads();

  // Warp pairing: warps (0,1) own tile blockIdx*2, warps (2,3) own +1.
  // Within a pair, `half` selects which 64 z-columns (8 n-tiles) this warp owns.
  const int g = blockIdx.x * 2 + (w >> 1);  // warp-pair tile of 32 batch rows
  const int half = w & 1;
  const int ob = half * 4;        // own k-tile base in A (this warp produces these)
  const int pb = ob ^ 4;          // partner's k-tile base

  const float* xbase = x + (long)(g * 32 + r) * XROW;
  const uint4* Utab = (const uint4*)(sm + OFF_U) + lane;
  const uint4* Wtab = (const uint4*)(sm + OFF_W) + lane;
  uint4* xch = (uint4*)(sm + OFF_X);
  uint4* own = xch + w * 256 + lane;              // 4KB slot per warp
  const uint4* par = xch + (w ^ 1) * 256 + lane;

  // A-fragments of [x_t | 1 | 0pad] per m-tile; converted at load
  unsigned xf[2][2][4];
  {
    const unsigned cpad = (q == 2) ? 0x00003C00u : 0u;  // cols 28..31 = 1,0,0,0
    if (q >= 2) {
      xf[0][1][2] = cpad; xf[0][1][3] = cpad;
      xf[1][1][2] = cpad; xf[1][1][3] = cpad;
    }
  }
  auto ldxf = [&](int t) {
#pragma unroll
    for (int m = 0; m < 2; m++) {
      const float* p0 = xbase + (m * 16) * XROW + t * kI + 2 * q;
      const float* p1 = p0 + 8 * XROW;
      xf[m][0][0] = packh2(*(const float2*)(p0));
      xf[m][0][1] = packh2(*(const float2*)(p1));
      xf[m][0][2] = packh2(*(const float2*)(p0 + 8));
      xf[m][0][3] = packh2(*(const float2*)(p1 + 8));
      xf[m][1][0] = packh2(*(const float2*)(p0 + 16));
      xf[m][1][1] = packh2(*(const float2*)(p1 + 16));
      if (q < 2) {  // q>=2 would read past row end on the last row
        xf[m][1][2] = packh2(*(const float2*)(p0 + 24));
        xf[m][1][3] = packh2(*(const float2*)(p1 + 24));
      }
    }
  };
  ldxf(0);

  // Full state A-fragments: own half written by tanh, partner half via SMEM.
  unsigned A[2][8][4];

#pragma unroll 1
  for (int t = 0; t < kT; t++) {
    // pull partner's half of S_{t-1} (written after bar#2 of t-1)
    if (t > 0) {
#pragma unroll
      for (int m = 0; m < 2; m++)
#pragma unroll
        for (int j = 0; j < 4; j++) {
          uint4 v = par[(m * 4 + j) * 32];
          A[m][pb + j][0] = v.x; A[m][pb + j][1] = v.y;
          A[m][pb + j][2] = v.z; A[m][pb + j][3] = v.w;
        }
    }
    unsigned C[2][8][2];  // fresh f16x2 accumulators, own 8 n-tiles only
    // U part: C = x_t @ U^T (+ biases) for this warp's n-half
#pragma unroll
    for (int i2 = 0; i2 < 4; i2++) {
      uint4 bb = Utab[(half * 4 + i2) * 32];
#pragma unroll
      for (int m = 0; m < 2; m++) {
        mmahz(C[m][2 * i2], xf[m][0], bb.x, bb.y);
        mmahz(C[m][2 * i2 + 1], xf[m][0], bb.z, bb.w);
      }
    }
#pragma unroll
    for (int i2 = 0; i2 < 4; i2++) {
      uint4 bb = Utab[(8 + half * 4 + i2) * 32];
#pragma unroll
      for (int m = 0; m < 2; m++) {
        mmah(C[m][2 * i2], xf[m][1], bb.x, bb.y);
        mmah(C[m][2 * i2 + 1], xf[m][1], bb.z, bb.w);
      }
    }
    // prefetch + convert x_{t+1} under the W MMAs
    if (t + 1 < kT) ldxf(t + 1);
    // W part: C += S_{t-1} @ W^T restricted to own n-half (full k)
    if (t > 0) {
#pragma unroll
      for (int kt = 0; kt < 8; kt++) {
#pragma unroll
        for (int i2 = 0; i2 < 4; i2++) {
          uint4 b = Wtab[(kt * 8 + half * 4 + i2) * 32];
#pragma unroll
          for (int m = 0; m < 2; m++) {
            mmah(C[m][2 * i2], A[m][kt], b.x, b.y);
            mmah(C[m][2 * i2 + 1], A[m][kt], b.z, b.w);
          }
        }
      }
    }
    // bar#1: everyone's partner-reads (loop head) done before new writes
    __syncthreads();
    // tanh -> own A half, and publish it for the partner (raw uint4 copy;
    // the f16 C layout IS the A-fragment layout, so no transpose anywhere)
#pragma unroll
    for (int m = 0; m < 2; m++)
#pragma unroll
      for (int j = 0; j < 4; j++) {
        unsigned a0 = th2(C[m][2 * j][0]), a1 = th2(C[m][2 * j][1]);
        unsigned a2 = th2(C[m][2 * j + 1][0]), a3 = th2(C[m][2 * j + 1][1]);
        A[m][ob + j][0] = a0; A[m][ob + j][1] = a1;
        A[m][ob + j][2] = a2; A[m][ob + j][3] = a3;
        own[(m * 4 + j) * 32] = make_uint4(a0, a1, a2, a3);
      }
    // bar#2: publishes visible before next iteration's partner-reads
    __syncthreads();
  }
  // final partner half for the output projection
#pragma unroll
  for (int m = 0; m < 2; m++)
#pragma unroll
    for (int j = 0; j < 4; j++) {
      uint4 v = par[(m * 4 + j) * 32];
      A[m][pb + j][0] = v.x; A[m][pb + j][1] = v.y;
      A[m][pb + j][2] = v.z; A[m][pb + j][3] = v.w;
    }

  // output: out = S @ V^T + V_b (fp32 accum). half 0 -> cols 0..7,
  // half 1 -> cols 8..9 (V padded to 16; each warp has full A).
  const uint4* Vtab = (const uint4*)(sm + OFF_V) + lane;
  if (half == 0) {
    const float vb0 = __ldg(Vb + 2 * q), vb1 = __ldg(Vb + 2 * q + 1);
#pragma unroll
    for (int m = 0; m < 2; m++) {
      float o0[4];
      uint4 b = Vtab[0];
      mma16z(o0, A[m][0], b.x, b.y);
#pragma unroll
      for (int kt = 1; kt < 8; kt++) {
        b = Vtab[kt * 32];
        mma16(o0, A[m][kt], b.x, b.y);
      }
      const int row0 = g * 32 + m * 16 + r;
      *(float2*)(out + row0 * kC + 2 * q) =
          make_float2(o0[0] + vb0, o0[1] + vb1);
      *(float2*)(out + (row0 + 8) * kC + 2 * q) =
          make_float2(o0[2] + vb0, o0[3] + vb1);
    }
  } else {
    const float vb8 = __ldg(Vb + 8), vb9 = __ldg(Vb + 9);
#pragma unroll
    for (int m = 0; m < 2; m++) {
      float o1[4];
      uint4 b = Vtab[0];
      mma16z(o1, A[m][0], b.z, b.w);
#pragma unroll
      for (int kt = 1; kt < 8; kt++) {
        b = Vtab[kt * 32];
        mma16(o1, A[m][kt], b.z, b.w);
      }
      if (q == 0) {
        const int row0 = g * 32 + m * 16 + r;
        *(float2*)(out + row0 * kC + 8) =
            make_float2(o1[0] + vb8, o1[1] + vb9);
        *(float2*)(out + (row0 + 8) * kC + 8) =
            make_float2(o1[2] + vb8, o1[3] + vb9);
      }
    }
  }
}

}  // namespace

extern "C" void kernel_launch(void* const* d_in, const int* in_sizes, int n_in,
                              void* d_out, int out_size) {
  (void)in_sizes; (void)n_in; (void)out_size;
  cudaFuncSetAttribute(rnn_kernel, cudaFuncAttributeMaxDynamicSharedMemorySize,
                       SMEM_TOTAL);
  rnn_kernel<<<GRID, THREADS, SMEM_TOTAL>>>(
      (const float*)d_in[0], (const float*)d_in[1], (const float*)d_in[2],
      (const float*)d_in[3], (const float*)d_in[4], (const float*)d_in[5],
      (const float*)d_in[6], (float*)d_out);
}

// round 16
// speedup vs baseline: 1.8193x; 1.8193x over previous
#include <cuda_runtime.h>
#include <cuda_fp16.h>
#include <cstdint>

#define DI __device__ __forceinline__

namespace {

constexpr int kT = 28;
constexpr int kI = 28;
constexpr int kH = 128;
constexpr int kC = 10;
constexpr int WARPS = 4;
constexpr int THREADS = WARPS * 32;                 // 128
constexpr int TILES = 32768 / 32;                   // 1024 warp-tiles (m32)
constexpr int GRID = TILES / WARPS;                 // 256
constexpr int XROW = kT * kI;                       // 784

// SMEM: paired-B fragment tables. One uint4 per lane per (kt, nt-pair)
// = B fragments for two consecutive n-tiles -> one LDS.128 feeds two MMAs
// (and with m32, each loaded B value feeds FOUR MMAs).
constexpr unsigned OFF_W = 0;                   // [8kt][8ntp][32 lane][16B] = 32768
constexpr unsigned OFF_U = 32768;               // [2kt][8ntp][32][16B]     = 8192
constexpr unsigned OFF_V = 32768 + 8192;        // [8kt][1ntp][32][16B]     = 4096
constexpr unsigned SMEM_TOTAL = OFF_V + 4096;   // 45056 -> 2 CTAs/SM

// pack two fp32 -> fp16x2 (lo = a, hi = b)
DI unsigned packh(float a, float b) {
  unsigned d;
  asm("cvt.rn.f16x2.f32 %0, %1, %2;" : "=r"(d) : "f"(b), "f"(a));
  return d;
}
DI unsigned packh2(float2 v) { return packh(v.x, v.y); }

DI unsigned th2(unsigned h2) {  // tanh on fp16x2, one MUFU per 2 elems
  unsigned r;
  asm("tanh.approx.f16x2 %0, %1;" : "=r"(r) : "r"(h2));
  return r;
}

// f16-accumulator MMA: D(f16x2 x2) += A(m16k16 f16) * B(k16n8 f16)
DI void mmah(unsigned* d, const unsigned* a, unsigned bx, unsigned by) {
  asm("mma.sync.aligned.m16n8k16.row.col.f16.f16.f16.f16 "
      "{%0,%1},{%2,%3,%4,%5},{%6,%7},{%0,%1};"
      : "+r"(d[0]), "+r"(d[1])
      : "r"(a[0]), "r"(a[1]), "r"(a[2]), "r"(a[3]), "r"(bx), "r"(by));
}
DI void mmahz(unsigned* d, const unsigned* a, unsigned bx, unsigned by) {
  asm("mma.sync.aligned.m16n8k16.row.col.f16.f16.f16.f16 "
      "{%0,%1},{%2,%3,%4,%5},{%6,%7},{%8,%8};"
      : "=r"(d[0]), "=r"(d[1])
      : "r"(a[0]), "r"(a[1]), "r"(a[2]), "r"(a[3]), "r"(bx), "r"(by),
        "r"(0u));
}
// f32-accumulator MMA (output projection only, outside the hot loop)
DI void mma16(float* c, const unsigned* a, unsigned bx, unsigned by) {
  asm("mma.sync.aligned.m16n8k16.row.col.f32.f16.f16.f32 "
      "{%0,%1,%2,%3},{%4,%5,%6,%7},{%8,%9},{%0,%1,%2,%3};"
      : "+f"(c[0]), "+f"(c[1]), "+f"(c[2]), "+f"(c[3])
      : "r"(a[0]), "r"(a[1]), "r"(a[2]), "r"(a[3]), "r"(bx), "r"(by));
}
DI void mma16z(float* c, const unsigned* a, unsigned bx, unsigned by) {
  asm("mma.sync.aligned.m16n8k16.row.col.f32.f16.f16.f32 "
      "{%0,%1,%2,%3},{%4,%5,%6,%7},{%8,%9},{%10,%10,%10,%10};"
      : "=f"(c[0]), "=f"(c[1]), "=f"(c[2]), "=f"(c[3])
      : "r"(a[0]), "r"(a[1]), "r"(a[2]), "r"(a[3]), "r"(bx), "r"(by),
        "f"(0.0f));
}

// B element (n,k) -> byte offset inside a paired table with `ntpn` nt-pairs
// (kt stride = ntpn * 32 uint4). W: ntpn=8, U: ntpn=8, V: ntpn=1.
DI unsigned bpos(int n, int k, int ntpn) {
  int kt = k >> 4, kk = k & 15, nt = n >> 3, rr = n & 7;
  int ntp = nt >> 1, sel = nt & 1;
  int ln = rr * 4 + ((kk >> 1) & 3);
  return (unsigned)((((kt * ntpn + ntp) * 32 + ln) << 4) + sel * 8 +
                    ((kk >> 3) & 1) * 4 + (kk & 1) * 2);
}

__global__ void __launch_bounds__(THREADS, 2) rnn_kernel(
    const float* __restrict__ x, const float* __restrict__ Uw,
    const float* __restrict__ Ub, const float* __restrict__ Ww,
    const float* __restrict__ Wb, const float* __restrict__ Vw,
    const float* __restrict__ Vb, float* __restrict__ out) {
  extern __shared__ __align__(16) char sm[];
  const int tid = threadIdx.x;
  const int w = tid >> 5, lane = tid & 31;
  const int r = lane >> 2, q = lane & 3;

  // ---- build fp16 paired-B fragment tables, biases folded into U col 28 ----
  for (int idx = tid; idx < kH * kH; idx += THREADS) {  // W^T[k][n] = Ww[n*128+k]
    int n = idx >> 7, k = idx & 127;
    *(__half*)(sm + OFF_W + bpos(n, k, 8)) = __float2half_rn(Ww[idx]);
  }
  for (int idx = tid; idx < kH * 32; idx += THREADS) {  // U^T padded K=32
    int n = idx >> 5, k = idx & 31;
    float v = (k < kI) ? Uw[n * kI + k] : ((k == kI) ? (Ub[n] + Wb[n]) : 0.0f);
    *(__half*)(sm + OFF_U + bpos(n, k, 8)) = __float2half_rn(v);
  }
  for (int idx = tid; idx < 16 * kH; idx += THREADS) {  // V^T padded N=16
    int n = idx >> 7, k = idx & 127;
    float v = (n < kC) ? Vw[n * kH + k] : 0.0f;
    *(__half*)(sm + OFF_V + bpos(n, k, 1)) = __float2half_rn(v);
  }
  __syncthreads();

  const int g = blockIdx.x * WARPS + w;  // global warp-tile (32 batch rows)

  // lane's A-fragment rows per m-tile: g*32 + m*16 + {r, r+8}
  const float* xbase = x + (long)(g * 32 + r) * XROW;
  const uint4* Utab = (const uint4*)(sm + OFF_U) + lane;
  const uint4* Wtab = (const uint4*)(sm + OFF_W) + lane;

  // A-fragments of [x_t | 1 | 0pad] per m-tile; converted at load
  unsigned xf[2][2][4];
  {
    const unsigned cpad = (q == 2) ? 0x00003C00u : 0u;  // cols 28..31 = 1,0,0,0
    if (q >= 2) {
      xf[0][1][2] = cpad; xf[0][1][3] = cpad;
      xf[1][1][2] = cpad; xf[1][1][3] = cpad;
    }
  }
  auto ldxf = [&](int t) {
#pragma unroll
    for (int m = 0; m < 2; m++) {
      const float* p0 = xbase + (m * 16) * XROW + t * kI + 2 * q;
      const float* p1 = p0 + 8 * XROW;
      xf[m][0][0] = packh2(*(const float2*)(p0));
      xf[m][0][1] = packh2(*(const float2*)(p1));
      xf[m][0][2] = packh2(*(const float2*)(p0 + 8));
      xf[m][0][3] = packh2(*(const float2*)(p1 + 8));
      xf[m][1][0] = packh2(*(const float2*)(p0 + 16));
      xf[m][1][1] = packh2(*(const float2*)(p1 + 16));
      if (q < 2) {  // q>=2 would read past row end on the last row
        xf[m][1][2] = packh2(*(const float2*)(p0 + 24));
        xf[m][1][3] = packh2(*(const float2*)(p1 + 24));
      }
    }
  };
  ldxf(0);

  // Persistent state: S_{t-1} A-fragments (fp16x2), one per m-tile.
  // Single array, no ping-pong (the tanh transform IS the move from C).
  unsigned A[2][8][4];

#pragma unroll 1
  for (int t = 0; t < kT; t++) {
    // Fresh f16x2 accumulators each iteration.
    unsigned C[2][16][2];
    // U part: C = x_t @ U^T (+ biases); kt=0 initializes.
    // Batch-of-4 B loads issued ahead of their consuming MMAs.
    {
      uint4 b0 = Utab[0 * 32], b1 = Utab[1 * 32];
      uint4 b2 = Utab[2 * 32], b3 = Utab[3 * 32];
#pragma unroll
      for (int half8 = 0; half8 < 2; half8++) {
        uint4 n0 = Utab[(half8 * 8 + 4) * 32], n1 = Utab[(half8 * 8 + 5) * 32];
        uint4 n2 = Utab[(half8 * 8 + 6) * 32], n3 = Utab[(half8 * 8 + 7) * 32];
        const uint4 bs[4] = {b0, b1, b2, b3};
#pragma unroll
        for (int j = 0; j < 4; j++) {
          int i = half8 * 8 + j;  // unused beyond clarity
          (void)i;
#pragma unroll
          for (int m = 0; m < 2; m++) {
            if (half8 == 0) {
              mmahz(C[m][2 * (half8 * 4 + j)], xf[m][0], bs[j].x, bs[j].y);
              mmahz(C[m][2 * (half8 * 4 + j) + 1], xf[m][0], bs[j].z, bs[j].w);
            }
          }
        }
        // second tier within this half8: use n0..n3
        const uint4 ns[4] = {n0, n1, n2, n3};
        if (half8 == 0) {
          // finish kt=0 (mmahz) for i = 4..7
#pragma unroll
          for (int j = 0; j < 4; j++)
#pragma unroll
            for (int m = 0; m < 2; m++) {
              mmahz(C[m][2 * (4 + j)], xf[m][0], ns[j].x, ns[j].y);
              mmahz(C[m][2 * (4 + j) + 1], xf[m][0], ns[j].z, ns[j].w);
            }
          // preload kt=1 first batch
          b0 = Utab[8 * 32]; b1 = Utab[9 * 32];
          b2 = Utab[10 * 32]; b3 = Utab[11 * 32];
        } else {
          // kt=1 (mmah accumulate): bs covered i=0..3, ns covers i=4..7
#pragma unroll
          for (int j = 0; j < 4; j++)
#pragma unroll
            for (int m = 0; m < 2; m++) {
              mmah(C[m][2 * (4 + j)], xf[m][1], ns[j].x, ns[j].y);
              mmah(C[m][2 * (4 + j) + 1], xf[m][1], ns[j].z, ns[j].w);
            }
        }
      }
      // note: kt=1 i=0..3 (the bs batch of half8==1) executed here:
      // (handled below to keep load->use distance; see W part preloads)
      uint4 c0 = Utab[8 * 32], c1 = Utab[9 * 32];
      uint4 c2 = Utab[10 * 32], c3 = Utab[11 * 32];
      const uint4 cs[4] = {c0, c1, c2, c3};
#pragma unroll
      for (int j = 0; j < 4; j++)
#pragma unroll
        for (int m = 0; m < 2; m++) {
          mmah(C[m][2 * j], xf[m][1], cs[j].x, cs[j].y);
          mmah(C[m][2 * j + 1], xf[m][1], cs[j].z, cs[j].w);
        }
    }
    // prefetch + convert x_{t+1} now (xf dead after U part): the 256 W-MMAs
    // below cover the DRAM latency of these LDGs.
    if (t + 1 < kT) ldxf(t + 1);
    // W part: C += S_{t-1} @ W^T (one LDS.128 feeds FOUR MMAs).
    // Batch-of-4 loads pipelined one batch ahead.
    if (t > 0) {
      uint4 b0 = Wtab[0], b1 = Wtab[1 * 32], b2 = Wtab[2 * 32], b3 = Wtab[3 * 32];
#pragma unroll
      for (int kt = 0; kt < 8; kt++) {
#pragma unroll
        for (int hb = 0; hb < 2; hb++) {
          // preload next batch while current batch feeds 16 MMAs
          const int cur = kt * 8 + hb * 4;
          uint4 n0, n1, n2, n3;
          if (cur + 4 < 64) {
            n0 = Wtab[(cur + 4) * 32]; n1 = Wtab[(cur + 5) * 32];
            n2 = Wtab[(cur + 6) * 32]; n3 = Wtab[(cur + 7) * 32];
          }
          const uint4 bs[4] = {b0, b1, b2, b3};
#pragma unroll
          for (int j = 0; j < 4; j++) {
            const int i = hb * 4 + j;
#pragma unroll
            for (int m = 0; m < 2; m++) {
              mmah(C[m][2 * i], A[m][kt], bs[j].x, bs[j].y);
              mmah(C[m][2 * i + 1], A[m][kt], bs[j].z, bs[j].w);
            }
          }
          if (cur + 4 < 64) { b0 = n0; b1 = n1; b2 = n2; b3 = n3; }
        }
      }
    }
    // transform = the move: A = tanh(C); f16x2 C rows align with A k-tiles.
#pragma unroll
    for (int m = 0; m < 2; m++)
#pragma unroll
      for (int kt = 0; kt < 8; kt++) {
        A[m][kt][0] = th2(C[m][2 * kt][0]);
        A[m][kt][1] = th2(C[m][2 * kt][1]);
        A[m][kt][2] = th2(C[m][2 * kt + 1][0]);
        A[m][kt][3] = th2(C[m][2 * kt + 1][1]);
      }
  }

  // output: out = S @ V^T + V_b (fp32 accum; N padded to 16, kt stride 32)
  const float vb0 = __ldg(Vb + 2 * q), vb1 = __ldg(Vb + 2 * q + 1);
  const float vb8 = __ldg(Vb + 8), vb9 = __ldg(Vb + 9);
#pragma unroll
  for (int m = 0; m < 2; m++) {
    float o0[4], o1[4];
    const uint4* bb = (const uint4*)(sm + OFF_V) + lane;
    uint4 b = bb[0];
    mma16z(o0, A[m][0], b.x, b.y);
    mma16z(o1, A[m][0], b.z, b.w);
#pragma unroll
    for (int kt = 1; kt < 8; kt++) {
      b = bb[kt * 32];
      mma16(o0, A[m][kt], b.x, b.y);
      mma16(o1, A[m][kt], b.z, b.w);
    }
    const int row0 = g * 32 + m * 16 + r;
    *(float2*)(out + row0 * kC + 2 * q) = make_float2(o0[0] + vb0, o0[1] + vb1);
    *(float2*)(out + (row0 + 8) * kC + 2 * q) =
        make_float2(o0[2] + vb0, o0[3] + vb1);
    if (q == 0) {
      *(float2*)(out + row0 * kC + 8) = make_float2(o1[0] + vb8, o1[1] + vb9);
      *(float2*)(out + (row0 + 8) * kC + 8) =
          make_float2(o1[2] + vb8, o1[3] + vb9);
    }
  }
}

}  // namespace

extern "C" void kernel_launch(void* const* d_in, const int* in_sizes, int n_in,
                              void* d_out, int out_size) {
  (void)in_sizes; (void)n_in; (void)out_size;
  cudaFuncSetAttribute(rnn_kernel, cudaFuncAttributeMaxDynamicSharedMemorySize,
                       SMEM_TOTAL);
  rnn_kernel<<<GRID, THREADS, SMEM_TOTAL>>>(
      (const float*)d_in[0], (const float*)d_in[1], (const float*)d_in[2],
      (const float*)d_in[3], (const float*)d_in[4], (const float*)d_in[5],
      (const float*)d_in[6], (float*)d_out);
}